// round 14
// baseline (speedup 1.0000x reference)
#include <cuda_runtime.h>
#include <cuda_fp16.h>
#include <math.h>

#define CN1 10000
#define CN2 10000
#define CF_IN 256
#define CHID 128
#define CNH 8
#define CDH 16
#define CNL 2
#define QKVW 384
#define EMAX 480000

// ---------------- scratch (static device globals) ----------------
__device__ float  g_h1[CN1 * CHID];
__device__ float  g_h2[CN2 * CHID];
__device__ __half g_qkv1[CN1 * QKVW];
__device__ __half g_qkv2[CN2 * QKVW];
__device__ float  g_agg1[CN1 * CHID], g_agg2[CN2 * CHID];
__device__ float  g_Em[CN1 * CHID * CNL], g_Ed[CN2 * CHID * CNL];
__device__ float  g_Wcat[CNL * 2 * CHID * QKVW];
__device__ float  g_bcat[CNL * 2 * QKVW];
// CSR scratch
__device__ int g_cnt12[CN2], g_cnt21[CN1];
__device__ int g_rp12[CN2 + 1], g_rp21[CN1 + 1];
__device__ int g_pos12[EMAX], g_pos21[EMAX];
__device__ int g_src12[EMAX], g_src21[EMAX];

// ---------------- helpers ----------------
__device__ __forceinline__ float gelu_f(float x) {
    float x3 = x * x * x;
    return 0.5f * x * (1.0f + tanhf(0.7978845608028654f * (x + 0.044715f * x3)));
}

__device__ __forceinline__ unsigned f2tf(float x) {
    unsigned r;
    asm("cvt.rna.tf32.f32 %0, %1;" : "=r"(r) : "f"(x));
    return r;
}

// ---------------- build packed weights (+ zero CSR counters in extra blocks) ----------------
__global__ void prep_cat(const float* __restrict__ Wq, const float* __restrict__ bq,
                         const float* __restrict__ Wk, const float* __restrict__ bk,
                         const float* __restrict__ Wv, const float* __restrict__ bv,
                         const float* __restrict__ arel, const float* __restrict__ mrel) {
    if (blockIdx.x >= 4) {
        int i = (blockIdx.x - 4) * blockDim.x + threadIdx.x;
        if (i < CN2) g_cnt12[i] = 0;
        if (i < CN1) g_cnt21[i] = 0;
        return;
    }
    int combo = blockIdx.x;
    const int WW = CHID * CHID;
    float* Wcat = g_Wcat + (size_t)combo * CHID * QKVW;
    float* bcat = g_bcat + combo * QKVW;
    int tid = threadIdx.x;
    for (int i = tid; i < CHID * QKVW; i += blockDim.x) {
        int c = i / QKVW, col = i % QKVW;
        float val;
        if (col < 128) {
            val = Wq[(size_t)combo * WW + c * CHID + col];
        } else if (col < 256) {
            int cc = col - 128, h = cc >> 4, e = cc & 15;
            const float* rel = arel + (size_t)combo * CNH * CDH * CDH + h * CDH * CDH;
            float acc = 0.f;
#pragma unroll
            for (int d = 0; d < CDH; d++)
                acc += Wk[(size_t)combo * WW + c * CHID + h * CDH + d] * rel[d * CDH + e];
            val = acc;
        } else {
            int cc = col - 256, h = cc >> 4, e = cc & 15;
            const float* rel = mrel + (size_t)combo * CNH * CDH * CDH + h * CDH * CDH;
            float acc = 0.f;
#pragma unroll
            for (int d = 0; d < CDH; d++)
                acc += Wv[(size_t)combo * WW + c * CHID + h * CDH + d] * rel[d * CDH + e];
            val = acc;
        }
        Wcat[i] = val;
    }
    if (tid < QKVW) {
        int col = tid;
        float val;
        if (col < 128) {
            val = bq[combo * CHID + col];
        } else if (col < 256) {
            int cc = col - 128, h = cc >> 4, e = cc & 15;
            const float* rel = arel + (size_t)combo * CNH * CDH * CDH + h * CDH * CDH;
            float acc = 0.f;
#pragma unroll
            for (int d = 0; d < CDH; d++) acc += bk[combo * CHID + h * CDH + d] * rel[d * CDH + e];
            val = acc;
        } else {
            int cc = col - 256, h = cc >> 4, e = cc & 15;
            const float* rel = mrel + (size_t)combo * CNH * CDH * CDH + h * CDH * CDH;
            float acc = 0.f;
#pragma unroll
            for (int d = 0; d < CDH; d++) acc += bv[combo * CHID + h * CDH + d] * rel[d * CDH + e];
            val = acc;
        }
        bcat[col] = val;
    }
}

// ---------------- CSR build ----------------
__global__ void csr_hist(const int* __restrict__ ei12, const int* __restrict__ ei21, int E) {
    int i = blockIdx.x * blockDim.x + threadIdx.x;
    if (i < E) {
        g_pos12[i] = atomicAdd(&g_cnt12[ei12[E + i]], 1);
    } else if (i < 2 * E) {
        int j = i - E;
        g_pos21[j] = atomicAdd(&g_cnt21[ei21[E + j]], 1);
    }
}

__global__ void __launch_bounds__(1024) csr_scan(int n) {
    int dir = blockIdx.x;
    const int* cnt = dir ? g_cnt21 : g_cnt12;
    int* rp  = dir ? g_rp21 : g_rp12;
    extern __shared__ int sh[];
    int* vals = sh;
    int* sums = sh + n;
    int t = threadIdx.x;
    for (int i = t; i < n; i += 1024) vals[i] = cnt[i];
    __syncthreads();
    int chunk = (n + 1023) / 1024;
    int s0 = t * chunk;
    int local = 0;
    for (int i = 0; i < chunk; i++) if (s0 + i < n) local += vals[s0 + i];
    sums[t] = local;
    __syncthreads();
    for (int off = 1; off < 1024; off <<= 1) {
        int v = (t >= off) ? sums[t - off] : 0;
        __syncthreads();
        sums[t] += v;
        __syncthreads();
    }
    int run = (t == 0) ? 0 : sums[t - 1];
    int total = sums[1023];
    __syncthreads();
    for (int i = 0; i < chunk; i++) if (s0 + i < n) {
        int c = vals[s0 + i];
        vals[s0 + i] = run;
        run += c;
    }
    __syncthreads();
    for (int i = t; i < n; i += 1024) rp[i] = vals[i];
    if (t == 0) rp[n] = total;
}

__global__ void csr_scatter(const int* __restrict__ ei12, const int* __restrict__ ei21, int E) {
    int i = blockIdx.x * blockDim.x + threadIdx.x;
    if (i < E) {
        int dst = ei12[E + i];
        g_src12[g_rp12[dst] + g_pos12[i]] = ei12[i];
    } else if (i < 2 * E) {
        int j = i - E;
        int dst = ei21[E + j];
        g_src21[g_rp21[dst] + g_pos21[j]] = ei21[j];
    }
}

// ---------------- TF32 tensor-core GEMM: two jobs per launch (blockIdx.z) ----------------
struct GJob {
    const float* A; int lda;
    const float* B; int ldb;
    const float* bias;
    float* Cf; int ldcf;
    __half* Ch; int ldch;
    int M, K;
    const float* hold; int ldh;
    const float* skipp;
};

__global__ void __launch_bounds__(256)
gemm_tc(GJob j0, GJob j1, int mode) {
    GJob jb = blockIdx.z ? j1 : j0;
    __shared__ unsigned As[128][36];
    __shared__ unsigned Bs[32][136];

    int tid  = threadIdx.x;
    int warp = tid >> 5;
    int lane = tid & 31;
    int g = lane >> 2;
    int c = lane & 3;
    int warp_m = warp >> 2;
    int warp_n = warp & 3;
    int m0 = blockIdx.x * 128;
    int n0 = blockIdx.y * 128;

    float acc[4][4][4];
#pragma unroll
    for (int mi = 0; mi < 4; mi++)
#pragma unroll
        for (int ni = 0; ni < 4; ni++)
#pragma unroll
            for (int r = 0; r < 4; r++) acc[mi][ni][r] = 0.f;

    for (int k0 = 0; k0 < jb.K; k0 += 32) {
#pragma unroll
        for (int i = 0; i < 4; i++) {
            int lin = tid + i * 256;
            int row = lin >> 3;
            int kc4 = (lin & 7) << 2;
            float4 v = make_float4(0.f, 0.f, 0.f, 0.f);
            int m = m0 + row;
            if (m < jb.M) {
                v = *(const float4*)(jb.A + (size_t)m * jb.lda + k0 + kc4);
                if (mode == 2) {
                    v.x = gelu_f(v.x); v.y = gelu_f(v.y);
                    v.z = gelu_f(v.z); v.w = gelu_f(v.w);
                }
            }
            uint4 t;
            t.x = f2tf(v.x); t.y = f2tf(v.y); t.z = f2tf(v.z); t.w = f2tf(v.w);
            *(uint4*)&As[row][kc4] = t;
        }
#pragma unroll
        for (int i = 0; i < 4; i++) {
            int lin = tid + i * 256;
            int kr  = lin >> 5;
            int nc4 = (lin & 31) << 2;
            float4 v = *(const float4*)(jb.B + (size_t)(k0 + kr) * jb.ldb + n0 + nc4);
            uint4 t;
            t.x = f2tf(v.x); t.y = f2tf(v.y); t.z = f2tf(v.z); t.w = f2tf(v.w);
            *(uint4*)&Bs[kr][nc4] = t;
        }
        __syncthreads();

#pragma unroll
        for (int ks = 0; ks < 4; ks++) {
            int kk = ks * 8;
            unsigned a[4][4];
#pragma unroll
            for (int mi = 0; mi < 4; mi++) {
                int r0 = warp_m * 64 + mi * 16 + g;
                a[mi][0] = As[r0][kk + c];
                a[mi][1] = As[r0 + 8][kk + c];
                a[mi][2] = As[r0][kk + c + 4];
                a[mi][3] = As[r0 + 8][kk + c + 4];
            }
            unsigned b[4][2];
#pragma unroll
            for (int ni = 0; ni < 4; ni++) {
                int nn = warp_n * 32 + ni * 8 + g;
                b[ni][0] = Bs[kk + c][nn];
                b[ni][1] = Bs[kk + c + 4][nn];
            }
#pragma unroll
            for (int mi = 0; mi < 4; mi++)
#pragma unroll
                for (int ni = 0; ni < 4; ni++) {
                    asm volatile(
                        "mma.sync.aligned.m16n8k8.row.col.f32.tf32.tf32.f32 "
                        "{%0,%1,%2,%3}, {%4,%5,%6,%7}, {%8,%9}, {%0,%1,%2,%3};\n"
                        : "+f"(acc[mi][ni][0]), "+f"(acc[mi][ni][1]),
                          "+f"(acc[mi][ni][2]), "+f"(acc[mi][ni][3])
                        : "r"(a[mi][0]), "r"(a[mi][1]), "r"(a[mi][2]), "r"(a[mi][3]),
                          "r"(b[ni][0]), "r"(b[ni][1]));
                }
        }
        __syncthreads();
    }

    float sg = 1.f, sg1 = 0.f;
    if (mode == 2) {
        sg = 1.0f / (1.0f + __expf(-*jb.skipp));
        sg1 = 1.0f - sg;
    }

#pragma unroll
    for (int mi = 0; mi < 4; mi++) {
#pragma unroll
        for (int half = 0; half < 2; half++) {
            int r = m0 + warp_m * 64 + mi * 16 + g + half * 8;
            if (r >= jb.M) continue;
#pragma unroll
            for (int ni = 0; ni < 4; ni++) {
                int n = n0 + warp_n * 32 + ni * 8 + 2 * c;
                float x0 = acc[mi][ni][half * 2 + 0] + jb.bias[n + 0];
                float x1 = acc[mi][ni][half * 2 + 1] + jb.bias[n + 1];
                if (mode == 1) {
                    x0 = fmaxf(x0, 0.f); x1 = fmaxf(x1, 0.f);
                    *(float2*)(jb.Cf + (size_t)r * jb.ldcf + n) = make_float2(x0, x1);
                } else if (mode == 2) {
                    const float* hp = jb.hold + (size_t)r * jb.ldh + n;
                    *(float2*)(jb.Cf + (size_t)r * jb.ldcf + n) =
                        make_float2(sg * x0 + sg1 * hp[0], sg * x1 + sg1 * hp[1]);
                } else {
                    __half2 p = __floats2half2_rn(x0, x1);
                    *(__half2*)(jb.Ch + (size_t)r * jb.ldch + n) = p;
                }
            }
        }
    }
}

// ---------------- CSR attention: warp = 1 dst, two 16-lane teams, half2 dot ----------------
struct AJob {
    const int* rp; const int* col;
    const __half* qkv_dst; const __half* qkv_src;
    const float* prior;
    float* agg;
    int n;
};

__device__ __forceinline__ void team_edge(uint4 kw, uint4 vw, bool valid,
                                          const __half2* qh, float scale,
                                          float* acc, float& ssum) {
    const __half2* kh = (const __half2*)&kw;
    __half2 p = __hmul2(qh[0], kh[0]);
    p = __hfma2(qh[1], kh[1], p);
    p = __hfma2(qh[2], kh[2], p);
    p = __hfma2(qh[3], kh[3], p);
    float2 df = __half22float2(p);
    float d = df.x + df.y;
    d += __shfl_xor_sync(0xffffffffu, d, 1);
    float e = valid ? __expf(d * scale) : 0.f;
    ssum += e;
    const __half2* vh = (const __half2*)&vw;
#pragma unroll
    for (int i = 0; i < 4; i++) {
        float2 vf = __half22float2(vh[i]);
        acc[2 * i]     += e * vf.x;
        acc[2 * i + 1] += e * vf.y;
    }
}

__global__ void __launch_bounds__(256, 4)
attend_csr(AJob a, AJob b) {
    int gw = (blockIdx.x * blockDim.x + threadIdx.x) >> 5;
    int lane = threadIdx.x & 31;
    int tlane = lane & 15;
    int team  = lane >> 4;
    int total = a.n + b.n;
    if (gw >= total) return;
    AJob jb = (gw < a.n) ? a : b;
    int dst = (gw < a.n) ? gw : gw - a.n;

    int start = __ldg(jb.rp + dst);
    int end   = __ldg(jb.rp + dst + 1);

    uint4 qw = __ldg((const uint4*)(jb.qkv_dst + (size_t)dst * QKVW) + tlane);
    __half2 qh[4];
    qh[0] = *(__half2*)&qw.x; qh[1] = *(__half2*)&qw.y;
    qh[2] = *(__half2*)&qw.z; qh[3] = *(__half2*)&qw.w;
    int h = tlane >> 1;
    float scale = __ldg(jb.prior + h) * 0.25f;

    float acc[8];
#pragma unroll
    for (int i = 0; i < 8; i++) acc[i] = 0.f;
    float ssum = 0.f;

    for (int base = start; base < end; base += 32) {
        int myc = (base + lane < end) ? __ldg(jb.col + base + lane) : 0;
        int cnt = min(32, end - base);
        int niter = (cnt + 1) >> 1;
        int it = 0;
        for (; it + 2 <= niter; it += 2) {
            int ja = 2 * it + team;
            int jx = ja + 2;
            int jcb = min(jx, cnt - 1);
            bool vb = jx < cnt;
            int sa = __shfl_sync(0xffffffffu, myc, ja);
            int sb = __shfl_sync(0xffffffffu, myc, jcb);
            const uint4* pa = (const uint4*)(jb.qkv_src + (size_t)sa * QKVW);
            const uint4* pb = (const uint4*)(jb.qkv_src + (size_t)sb * QKVW);
            uint4 ka = __ldg(pa + 16 + tlane), va = __ldg(pa + 32 + tlane);
            uint4 kb = __ldg(pb + 16 + tlane), vbv = __ldg(pb + 32 + tlane);
            team_edge(ka, va, true, qh, scale, acc, ssum);
            team_edge(kb, vbv, vb, qh, scale, acc, ssum);
        }
        for (; it < niter; it++) {
            int j = 2 * it + team;
            int jc = min(j, cnt - 1);
            bool v_ = j < cnt;
            int s0 = __shfl_sync(0xffffffffu, myc, jc);
            const uint4* p0 = (const uint4*)(jb.qkv_src + (size_t)s0 * QKVW);
            uint4 k0 = __ldg(p0 + 16 + tlane), v0 = __ldg(p0 + 32 + tlane);
            team_edge(k0, v0, v_, qh, scale, acc, ssum);
        }
    }

#pragma unroll
    for (int i = 0; i < 8; i++) acc[i] += __shfl_xor_sync(0xffffffffu, acc[i], 16);
    ssum += __shfl_xor_sync(0xffffffffu, ssum, 16);

    if (team == 0) {
        float inv = 1.0f / (ssum + 1e-16f);
        float* op = jb.agg + (size_t)dst * CHID + tlane * 8;
        *(float4*)(op)     = make_float4(acc[0] * inv, acc[1] * inv, acc[2] * inv, acc[3] * inv);
        *(float4*)(op + 4) = make_float4(acc[4] * inv, acc[5] * inv, acc[6] * inv, acc[7] * inv);
    }
}

// ---------------- PROBE: quarter-size clone of attend_csr, launched at slot #4 so the
// fixed ncu capture window finally profiles the attend workload. Reads the CSR/qkv state
// from the previous replay (identical data); clamps make the single correctness-run
// execution (garbage CSR) bounded and memory-safe. Writes agg, which the real
// attend_csr fully overwrites afterwards -> no output effect.
__global__ void __launch_bounds__(256, 4)
attend_probe(AJob a, AJob b, int emax, int nsrc_a, int nsrc_b) {
    int gw = (blockIdx.x * blockDim.x + threadIdx.x) >> 5;
    int lane = threadIdx.x & 31;
    int tlane = lane & 15;
    int team  = lane >> 4;
    int total = a.n + b.n;
    if (gw >= total) return;
    AJob jb = (gw < a.n) ? a : b;
    int nsrc = (gw < a.n) ? nsrc_a : nsrc_b;
    int dst = (gw < a.n) ? gw : gw - a.n;

    int start = __ldg(jb.rp + dst);
    int end   = __ldg(jb.rp + dst + 1);
    start = max(0, min(start, emax));
    end   = max(start, min(end, min(emax, start + 256)));   // bounded on garbage

    uint4 qw = __ldg((const uint4*)(jb.qkv_dst + (size_t)dst * QKVW) + tlane);
    __half2 qh[4];
    qh[0] = *(__half2*)&qw.x; qh[1] = *(__half2*)&qw.y;
    qh[2] = *(__half2*)&qw.z; qh[3] = *(__half2*)&qw.w;
    int h = tlane >> 1;
    float scale = __ldg(jb.prior + h) * 0.25f;

    float acc[8];
#pragma unroll
    for (int i = 0; i < 8; i++) acc[i] = 0.f;
    float ssum = 0.f;

    for (int base = start; base < end; base += 32) {
        int myc = (base + lane < end) ? __ldg(jb.col + base + lane) : 0;
        int cnt = min(32, end - base);
        int niter = (cnt + 1) >> 1;
        for (int it = 0; it < niter; it++) {
            int j = 2 * it + team;
            int jc = min(j, cnt - 1);
            bool v_ = j < cnt;
            int s0 = __shfl_sync(0xffffffffu, myc, jc);
            s0 = max(0, min(s0, nsrc - 1));                 // safe on garbage
            const uint4* p0 = (const uint4*)(jb.qkv_src + (size_t)s0 * QKVW);
            uint4 k0 = __ldg(p0 + 16 + tlane), v0 = __ldg(p0 + 32 + tlane);
            team_edge(k0, v0, v_, qh, scale, acc, ssum);
        }
    }

#pragma unroll
    for (int i = 0; i < 8; i++) acc[i] += __shfl_xor_sync(0xffffffffu, acc[i], 16);
    ssum += __shfl_xor_sync(0xffffffffu, ssum, 16);

    if (team == 0) {
        float inv = 1.0f / (ssum + 1e-16f);
        float* op = jb.agg + (size_t)dst * CHID + tlane * 8;
        *(float4*)(op)     = make_float4(acc[0] * inv, acc[1] * inv, acc[2] * inv, acc[3] * inv);
        *(float4*)(op + 4) = make_float4(acc[4] * inv, acc[5] * inv, acc[6] * inv, acc[7] * inv);
    }
}

// ---------------- final pair scores ----------------
__global__ void __launch_bounds__(256)
pred_kernel(const int* __restrict__ pidx, int P, float* __restrict__ out) {
    int warp = (blockIdx.x * blockDim.x + threadIdx.x) >> 5;
    int lane = threadIdx.x & 31;
    if (warp >= P) return;
    int i = pidx[warp];
    int j = pidx[P + warp];
    const float4* em = (const float4*)(g_Em + (size_t)i * (CHID * CNL));
    const float4* ed = (const float4*)(g_Ed + (size_t)j * (CHID * CNL));
    float4 a0 = em[lane],      b0 = ed[lane];
    float4 a1 = em[32 + lane], b1 = ed[32 + lane];
    float d = a0.x * b0.x + a0.y * b0.y + a0.z * b0.z + a0.w * b0.w
            + a1.x * b1.x + a1.y * b1.y + a1.z * b1.z + a1.w * b1.w;
#pragma unroll
    for (int o = 16; o > 0; o >>= 1) d += __shfl_xor_sync(0xffffffffu, d, o);
    if (lane == 0) out[warp] = d;
}

// ---------------- host driver ----------------
extern "C" void kernel_launch(void* const* d_in, const int* in_sizes, int n_in,
                              void* d_out, int out_size) {
    const float* x1    = (const float*)d_in[0];
    const float* x2    = (const float*)d_in[1];
    const int*   ei12  = (const int*)d_in[2];
    const int*   ei21  = (const int*)d_in[3];
    const int*   pidx  = (const int*)d_in[4];
    const float* Win1  = (const float*)d_in[5];
    const float* bin1  = (const float*)d_in[6];
    const float* Win2  = (const float*)d_in[7];
    const float* bin2  = (const float*)d_in[8];
    const float* Wk    = (const float*)d_in[9];
    const float* bk    = (const float*)d_in[10];
    const float* Wq    = (const float*)d_in[11];
    const float* bq    = (const float*)d_in[12];
    const float* Wv    = (const float*)d_in[13];
    const float* bv    = (const float*)d_in[14];
    const float* Wa    = (const float*)d_in[15];
    const float* ba    = (const float*)d_in[16];
    const float* skip  = (const float*)d_in[17];
    const float* arel  = (const float*)d_in[18];
    const float* mrel  = (const float*)d_in[19];
    const float* prior = (const float*)d_in[20];
    float* out = (float*)d_out;

    const int E = in_sizes[2] / 2;
    const int P = in_sizes[4] / 2;

    float *h1, *h2, *agg1, *agg2, *Em, *Ed, *Wcat, *bcat;
    __half *qkv1, *qkv2;
    int *rp12, *rp21, *src12, *src21;
    cudaGetSymbolAddress((void**)&h1,   g_h1);
    cudaGetSymbolAddress((void**)&h2,   g_h2);
    cudaGetSymbolAddress((void**)&qkv1, g_qkv1);
    cudaGetSymbolAddress((void**)&qkv2, g_qkv2);
    cudaGetSymbolAddress((void**)&agg1, g_agg1);
    cudaGetSymbolAddress((void**)&agg2, g_agg2);
    cudaGetSymbolAddress((void**)&Em,   g_Em);
    cudaGetSymbolAddress((void**)&Ed,   g_Ed);
    cudaGetSymbolAddress((void**)&Wcat, g_Wcat);
    cudaGetSymbolAddress((void**)&bcat, g_bcat);
    cudaGetSymbolAddress((void**)&rp12, g_rp12);
    cudaGetSymbolAddress((void**)&rp21, g_rp21);
    cudaGetSymbolAddress((void**)&src12, g_src12);
    cudaGetSymbolAddress((void**)&src21, g_src21);

    const int WW = CHID * CHID;

    prep_cat<<<4 + (CN1 + 255) / 256, 256>>>(Wq, bq, Wk, bk, Wv, bv, arel, mrel);   // #1
    csr_hist<<<(2 * E + 255) / 256, 256>>>(ei12, ei21, E);                          // #2
    {
        int shbytes = (CN1 + 1024) * sizeof(int);
        csr_scan<<<2, 1024, shbytes>>>(CN1);                                        // #3
    }
    // #4: measurement probe (quarter-size attend on prior-replay state)
    {
        AJob a = { rp12, src12, qkv2, qkv1, prior, agg2, CN2 / 4 };
        AJob b = { rp21, src21, qkv1, qkv2, prior + CNH, agg1, CN1 / 4 };
        int warps = CN1 / 4 + CN2 / 4;
        attend_probe<<<(warps * 32 + 255) / 256, 256>>>(a, b, E, CN1, CN2);
    }
    csr_scatter<<<(2 * E + 255) / 256, 256>>>(ei12, ei21, E);                       // #5

    {
        GJob j0 = { x1, CF_IN, Win1, CHID, bin1, h1, CHID, nullptr, 0, CN1, CF_IN, nullptr, 0, nullptr };
        GJob j1 = { x2, CF_IN, Win2, CHID, bin2, h2, CHID, nullptr, 0, CN2, CF_IN, nullptr, 0, nullptr };
        gemm_tc<<<dim3((CN1 + 127) / 128, 1, 2), 256>>>(j0, j1, 1);
    }

    for (int l = 0; l < CNL; l++) {
        const float* A1 = (l == 0) ? h1 : Em;
        const float* A2 = (l == 0) ? h2 : Ed;
        int lda = (l == 0) ? CHID : CNL * CHID;
        int c0 = l * 2 + 0, c1 = l * 2 + 1;

        {
            GJob j0 = { A1, lda, Wcat + (size_t)c0 * CHID * QKVW, QKVW, bcat + c0 * QKVW,
                        nullptr, 0, qkv1, QKVW, CN1, CHID, nullptr, 0, nullptr };
            GJob j1 = { A2, lda, Wcat + (size_t)c1 * CHID * QKVW, QKVW, bcat + c1 * QKVW,
                        nullptr, 0, qkv2, QKVW, CN2, CHID, nullptr, 0, nullptr };
            gemm_tc<<<dim3((CN1 + 127) / 128, 3, 2), 256>>>(j0, j1, 3);
        }

        {
            AJob a = { rp12, src12, qkv2, qkv1, prior + c0 * CNH, agg2, CN2 };
            AJob b = { rp21, src21, qkv1, qkv2, prior + c1 * CNH, agg1, CN1 };
            int warps = CN1 + CN2;
            attend_csr<<<(warps * 32 + 255) / 256, 256>>>(a, b);
        }

        {
            const float* hold1 = (l == 0) ? h1 : Em;
            const float* hold2 = (l == 0) ? h2 : Ed;
            int ldh = (l == 0) ? CHID : CNL * CHID;
            GJob j0 = { agg1, CHID, Wa + (size_t)c0 * WW, CHID, ba + c0 * CHID,
                        Em + l * CHID, CNL * CHID, nullptr, 0, CN1, CHID, hold1, ldh, skip + c0 };
            GJob j1 = { agg2, CHID, Wa + (size_t)c1 * WW, CHID, ba + c1 * CHID,
                        Ed + l * CHID, CNL * CHID, nullptr, 0, CN2, CHID, hold2, ldh, skip + c1 };
            gemm_tc<<<dim3((CN1 + 127) / 128, 1, 2), 256>>>(j0, j1, 2);
        }
    }

    pred_kernel<<<(P * 32 + 255) / 256, 256>>>(pidx, P, out);
}

// round 15
// speedup vs baseline: 1.2636x; 1.2636x over previous
#include <cuda_runtime.h>
#include <cuda_fp16.h>
#include <math.h>

#define CN1 10000
#define CN2 10000
#define CF_IN 256
#define CHID 128
#define CNH 8
#define CDH 16
#define CNL 2
#define QKVW 384
#define EMAX 480000

// ---------------- scratch (static device globals) ----------------
__device__ float  g_h1[CN1 * CHID];
__device__ float  g_h2[CN2 * CHID];
__device__ __half g_qkv1[CN1 * QKVW];
__device__ __half g_qkv2[CN2 * QKVW];
__device__ float  g_agg1[CN1 * CHID], g_agg2[CN2 * CHID];
__device__ float  g_Em[CN1 * CHID * CNL], g_Ed[CN2 * CHID * CNL];
__device__ float  g_Wcat[CNL * 2 * CHID * QKVW];
__device__ float  g_bcat[CNL * 2 * QKVW];
// CSR scratch
__device__ int g_cnt12[CN2], g_cnt21[CN1];
__device__ int g_rp12[CN2 + 1], g_rp21[CN1 + 1];
__device__ int g_pos12[EMAX], g_pos21[EMAX];
__device__ int g_src12[EMAX], g_src21[EMAX];

// ---------------- helpers ----------------
__device__ __forceinline__ float gelu_f(float x) {
    float x3 = x * x * x;
    return 0.5f * x * (1.0f + tanhf(0.7978845608028654f * (x + 0.044715f * x3)));
}

__device__ __forceinline__ unsigned f2tf(float x) {
    unsigned r;
    asm("cvt.rna.tf32.f32 %0, %1;" : "=r"(r) : "f"(x));
    return r;
}

// ---------------- build packed weights: parallel over 32 blocks + CSR-zero blocks ----------------
// blocks [0,32): weight chunks (combo = b>>3, part = b&7); blocks >= 32: zero CSR counters.
__global__ void prep_cat(const float* __restrict__ Wq, const float* __restrict__ bq,
                         const float* __restrict__ Wk, const float* __restrict__ bk,
                         const float* __restrict__ Wv, const float* __restrict__ bv,
                         const float* __restrict__ arel, const float* __restrict__ mrel) {
    if (blockIdx.x >= 32) {
        int i = (blockIdx.x - 32) * blockDim.x + threadIdx.x;
        if (i < CN2) g_cnt12[i] = 0;
        if (i < CN1) g_cnt21[i] = 0;
        return;
    }
    int combo = blockIdx.x >> 3;
    int part  = blockIdx.x & 7;
    const int WW = CHID * CHID;
    const int CHUNK = CHID * QKVW / 8;   // 6144
    float* Wcat = g_Wcat + (size_t)combo * CHID * QKVW;
    float* bcat = g_bcat + combo * QKVW;
    int tid = threadIdx.x;
    for (int i = part * CHUNK + tid; i < (part + 1) * CHUNK; i += blockDim.x) {
        int c = i / QKVW, col = i % QKVW;
        float val;
        if (col < 128) {
            val = Wq[(size_t)combo * WW + c * CHID + col];
        } else if (col < 256) {
            int cc = col - 128, h = cc >> 4, e = cc & 15;
            const float* rel = arel + (size_t)combo * CNH * CDH * CDH + h * CDH * CDH;
            float acc = 0.f;
#pragma unroll
            for (int d = 0; d < CDH; d++)
                acc += Wk[(size_t)combo * WW + c * CHID + h * CDH + d] * rel[d * CDH + e];
            val = acc;
        } else {
            int cc = col - 256, h = cc >> 4, e = cc & 15;
            const float* rel = mrel + (size_t)combo * CNH * CDH * CDH + h * CDH * CDH;
            float acc = 0.f;
#pragma unroll
            for (int d = 0; d < CDH; d++)
                acc += Wv[(size_t)combo * WW + c * CHID + h * CDH + d] * rel[d * CDH + e];
            val = acc;
        }
        Wcat[i] = val;
    }
    if (part == 0 && tid < QKVW) {
        int col = tid;
        float val;
        if (col < 128) {
            val = bq[combo * CHID + col];
        } else if (col < 256) {
            int cc = col - 128, h = cc >> 4, e = cc & 15;
            const float* rel = arel + (size_t)combo * CNH * CDH * CDH + h * CDH * CDH;
            float acc = 0.f;
#pragma unroll
            for (int d = 0; d < CDH; d++) acc += bk[combo * CHID + h * CDH + d] * rel[d * CDH + e];
            val = acc;
        } else {
            int cc = col - 256, h = cc >> 4, e = cc & 15;
            const float* rel = mrel + (size_t)combo * CNH * CDH * CDH + h * CDH * CDH;
            float acc = 0.f;
#pragma unroll
            for (int d = 0; d < CDH; d++) acc += bv[combo * CHID + h * CDH + d] * rel[d * CDH + e];
            val = acc;
        }
        bcat[col] = val;
    }
}

// ---------------- CSR build: thread i handles edge i in BOTH directions (2 indep chains) ----------------
__global__ void csr_hist(const int* __restrict__ ei12, const int* __restrict__ ei21, int E) {
    int i = blockIdx.x * blockDim.x + threadIdx.x;
    if (i < E) {
        g_pos12[i] = atomicAdd(&g_cnt12[ei12[E + i]], 1);
        g_pos21[i] = atomicAdd(&g_cnt21[ei21[E + i]], 1);
    }
}

__global__ void __launch_bounds__(1024) csr_scan(int n) {
    int dir = blockIdx.x;
    const int* cnt = dir ? g_cnt21 : g_cnt12;
    int* rp  = dir ? g_rp21 : g_rp12;
    extern __shared__ int sh[];
    int* vals = sh;
    int* sums = sh + n;
    int t = threadIdx.x;
    for (int i = t; i < n; i += 1024) vals[i] = cnt[i];
    __syncthreads();
    int chunk = (n + 1023) / 1024;
    int s0 = t * chunk;
    int local = 0;
    for (int i = 0; i < chunk; i++) if (s0 + i < n) local += vals[s0 + i];
    sums[t] = local;
    __syncthreads();
    for (int off = 1; off < 1024; off <<= 1) {
        int v = (t >= off) ? sums[t - off] : 0;
        __syncthreads();
        sums[t] += v;
        __syncthreads();
    }
    int run = (t == 0) ? 0 : sums[t - 1];
    int total = sums[1023];
    __syncthreads();
    for (int i = 0; i < chunk; i++) if (s0 + i < n) {
        int c = vals[s0 + i];
        vals[s0 + i] = run;
        run += c;
    }
    __syncthreads();
    for (int i = t; i < n; i += 1024) rp[i] = vals[i];
    if (t == 0) rp[n] = total;
}

__global__ void csr_scatter(const int* __restrict__ ei12, const int* __restrict__ ei21, int E) {
    int i = blockIdx.x * blockDim.x + threadIdx.x;
    if (i < E) {
        int d1 = ei12[E + i];
        int d2 = ei21[E + i];
        g_src12[g_rp12[d1] + g_pos12[i]] = ei12[i];
        g_src21[g_rp21[d2] + g_pos21[i]] = ei21[i];
    }
}

// ---------------- TF32 tensor-core GEMM: two jobs per launch (blockIdx.z) ----------------
struct GJob {
    const float* A; int lda;
    const float* B; int ldb;
    const float* bias;
    float* Cf; int ldcf;
    __half* Ch; int ldch;
    int M, K;
    const float* hold; int ldh;
    const float* skipp;
};

__global__ void __launch_bounds__(256)
gemm_tc(GJob j0, GJob j1, int mode) {
    GJob jb = blockIdx.z ? j1 : j0;
    __shared__ unsigned As[128][36];
    __shared__ unsigned Bs[32][136];

    int tid  = threadIdx.x;
    int warp = tid >> 5;
    int lane = tid & 31;
    int g = lane >> 2;
    int c = lane & 3;
    int warp_m = warp >> 2;
    int warp_n = warp & 3;
    int m0 = blockIdx.x * 128;
    int n0 = blockIdx.y * 128;

    float acc[4][4][4];
#pragma unroll
    for (int mi = 0; mi < 4; mi++)
#pragma unroll
        for (int ni = 0; ni < 4; ni++)
#pragma unroll
            for (int r = 0; r < 4; r++) acc[mi][ni][r] = 0.f;

    for (int k0 = 0; k0 < jb.K; k0 += 32) {
#pragma unroll
        for (int i = 0; i < 4; i++) {
            int lin = tid + i * 256;
            int row = lin >> 3;
            int kc4 = (lin & 7) << 2;
            float4 v = make_float4(0.f, 0.f, 0.f, 0.f);
            int m = m0 + row;
            if (m < jb.M) {
                v = *(const float4*)(jb.A + (size_t)m * jb.lda + k0 + kc4);
                if (mode == 2) {
                    v.x = gelu_f(v.x); v.y = gelu_f(v.y);
                    v.z = gelu_f(v.z); v.w = gelu_f(v.w);
                }
            }
            uint4 t;
            t.x = f2tf(v.x); t.y = f2tf(v.y); t.z = f2tf(v.z); t.w = f2tf(v.w);
            *(uint4*)&As[row][kc4] = t;
        }
#pragma unroll
        for (int i = 0; i < 4; i++) {
            int lin = tid + i * 256;
            int kr  = lin >> 5;
            int nc4 = (lin & 31) << 2;
            float4 v = *(const float4*)(jb.B + (size_t)(k0 + kr) * jb.ldb + n0 + nc4);
            uint4 t;
            t.x = f2tf(v.x); t.y = f2tf(v.y); t.z = f2tf(v.z); t.w = f2tf(v.w);
            *(uint4*)&Bs[kr][nc4] = t;
        }
        __syncthreads();

#pragma unroll
        for (int ks = 0; ks < 4; ks++) {
            int kk = ks * 8;
            unsigned a[4][4];
#pragma unroll
            for (int mi = 0; mi < 4; mi++) {
                int r0 = warp_m * 64 + mi * 16 + g;
                a[mi][0] = As[r0][kk + c];
                a[mi][1] = As[r0 + 8][kk + c];
                a[mi][2] = As[r0][kk + c + 4];
                a[mi][3] = As[r0 + 8][kk + c + 4];
            }
            unsigned b[4][2];
#pragma unroll
            for (int ni = 0; ni < 4; ni++) {
                int nn = warp_n * 32 + ni * 8 + g;
                b[ni][0] = Bs[kk + c][nn];
                b[ni][1] = Bs[kk + c + 4][nn];
            }
#pragma unroll
            for (int mi = 0; mi < 4; mi++)
#pragma unroll
                for (int ni = 0; ni < 4; ni++) {
                    asm volatile(
                        "mma.sync.aligned.m16n8k8.row.col.f32.tf32.tf32.f32 "
                        "{%0,%1,%2,%3}, {%4,%5,%6,%7}, {%8,%9}, {%0,%1,%2,%3};\n"
                        : "+f"(acc[mi][ni][0]), "+f"(acc[mi][ni][1]),
                          "+f"(acc[mi][ni][2]), "+f"(acc[mi][ni][3])
                        : "r"(a[mi][0]), "r"(a[mi][1]), "r"(a[mi][2]), "r"(a[mi][3]),
                          "r"(b[ni][0]), "r"(b[ni][1]));
                }
        }
        __syncthreads();
    }

    float sg = 1.f, sg1 = 0.f;
    if (mode == 2) {
        sg = 1.0f / (1.0f + __expf(-*jb.skipp));
        sg1 = 1.0f - sg;
    }

#pragma unroll
    for (int mi = 0; mi < 4; mi++) {
#pragma unroll
        for (int half = 0; half < 2; half++) {
            int r = m0 + warp_m * 64 + mi * 16 + g + half * 8;
            if (r >= jb.M) continue;
#pragma unroll
            for (int ni = 0; ni < 4; ni++) {
                int n = n0 + warp_n * 32 + ni * 8 + 2 * c;
                float x0 = acc[mi][ni][half * 2 + 0] + jb.bias[n + 0];
                float x1 = acc[mi][ni][half * 2 + 1] + jb.bias[n + 1];
                if (mode == 1) {
                    x0 = fmaxf(x0, 0.f); x1 = fmaxf(x1, 0.f);
                    *(float2*)(jb.Cf + (size_t)r * jb.ldcf + n) = make_float2(x0, x1);
                } else if (mode == 2) {
                    const float* hp = jb.hold + (size_t)r * jb.ldh + n;
                    *(float2*)(jb.Cf + (size_t)r * jb.ldcf + n) =
                        make_float2(sg * x0 + sg1 * hp[0], sg * x1 + sg1 * hp[1]);
                } else {
                    __half2 p = __floats2half2_rn(x0, x1);
                    *(__half2*)(jb.Ch + (size_t)r * jb.ldch + n) = p;
                }
            }
        }
    }
}

// ---------------- CSR attention: warp = 1 dst, two 16-lane teams, serial loop (probe-validated) ----------------
struct AJob {
    const int* rp; const int* col;
    const __half* qkv_dst; const __half* qkv_src;
    const float* prior;
    float* agg;
    int n;
};

__device__ __forceinline__ void team_edge(uint4 kw, uint4 vw, bool valid,
                                          const __half2* qh, float scale,
                                          float* acc, float& ssum) {
    const __half2* kh = (const __half2*)&kw;
    __half2 p = __hmul2(qh[0], kh[0]);
    p = __hfma2(qh[1], kh[1], p);
    p = __hfma2(qh[2], kh[2], p);
    p = __hfma2(qh[3], kh[3], p);
    float2 df = __half22float2(p);
    float d = df.x + df.y;
    d += __shfl_xor_sync(0xffffffffu, d, 1);
    float e = valid ? __expf(d * scale) : 0.f;
    ssum += e;
    const __half2* vh = (const __half2*)&vw;
#pragma unroll
    for (int i = 0; i < 4; i++) {
        float2 vf = __half22float2(vh[i]);
        acc[2 * i]     += e * vf.x;
        acc[2 * i + 1] += e * vf.y;
    }
}

__global__ void __launch_bounds__(128, 8)
attend_csr(AJob a, AJob b) {
    int gw = (blockIdx.x * blockDim.x + threadIdx.x) >> 5;
    int lane = threadIdx.x & 31;
    int tlane = lane & 15;
    int team  = lane >> 4;
    int total = a.n + b.n;
    if (gw >= total) return;
    AJob jb = (gw < a.n) ? a : b;
    int dst = (gw < a.n) ? gw : gw - a.n;

    int start = __ldg(jb.rp + dst);
    int end   = __ldg(jb.rp + dst + 1);

    uint4 qw = __ldg((const uint4*)(jb.qkv_dst + (size_t)dst * QKVW) + tlane);
    __half2 qh[4];
    qh[0] = *(__half2*)&qw.x; qh[1] = *(__half2*)&qw.y;
    qh[2] = *(__half2*)&qw.z; qh[3] = *(__half2*)&qw.w;
    int h = tlane >> 1;
    float scale = __ldg(jb.prior + h) * 0.25f;

    float acc[8];
#pragma unroll
    for (int i = 0; i < 8; i++) acc[i] = 0.f;
    float ssum = 0.f;

    for (int base = start; base < end; base += 32) {
        int myc = (base + lane < end) ? __ldg(jb.col + base + lane) : 0;
        int cnt = min(32, end - base);
        int niter = (cnt + 1) >> 1;
        for (int it = 0; it < niter; it++) {
            int j = 2 * it + team;
            int jc = min(j, cnt - 1);
            bool v_ = j < cnt;
            int s0 = __shfl_sync(0xffffffffu, myc, jc);
            const uint4* p0 = (const uint4*)(jb.qkv_src + (size_t)s0 * QKVW);
            uint4 k0 = __ldg(p0 + 16 + tlane), v0 = __ldg(p0 + 32 + tlane);
            team_edge(k0, v0, v_, qh, scale, acc, ssum);
        }
    }

#pragma unroll
    for (int i = 0; i < 8; i++) acc[i] += __shfl_xor_sync(0xffffffffu, acc[i], 16);
    ssum += __shfl_xor_sync(0xffffffffu, ssum, 16);

    if (team == 0) {
        float inv = 1.0f / (ssum + 1e-16f);
        float* op = jb.agg + (size_t)dst * CHID + tlane * 8;
        *(float4*)(op)     = make_float4(acc[0] * inv, acc[1] * inv, acc[2] * inv, acc[3] * inv);
        *(float4*)(op + 4) = make_float4(acc[4] * inv, acc[5] * inv, acc[6] * inv, acc[7] * inv);
    }
}

// ---------------- final pair scores ----------------
__global__ void __launch_bounds__(256)
pred_kernel(const int* __restrict__ pidx, int P, float* __restrict__ out) {
    int warp = (blockIdx.x * blockDim.x + threadIdx.x) >> 5;
    int lane = threadIdx.x & 31;
    if (warp >= P) return;
    int i = pidx[warp];
    int j = pidx[P + warp];
    const float4* em = (const float4*)(g_Em + (size_t)i * (CHID * CNL));
    const float4* ed = (const float4*)(g_Ed + (size_t)j * (CHID * CNL));
    float4 a0 = em[lane],      b0 = ed[lane];
    float4 a1 = em[32 + lane], b1 = ed[32 + lane];
    float d = a0.x * b0.x + a0.y * b0.y + a0.z * b0.z + a0.w * b0.w
            + a1.x * b1.x + a1.y * b1.y + a1.z * b1.z + a1.w * b1.w;
#pragma unroll
    for (int o = 16; o > 0; o >>= 1) d += __shfl_xor_sync(0xffffffffu, d, o);
    if (lane == 0) out[warp] = d;
}

// ---------------- host driver ----------------
extern "C" void kernel_launch(void* const* d_in, const int* in_sizes, int n_in,
                              void* d_out, int out_size) {
    const float* x1    = (const float*)d_in[0];
    const float* x2    = (const float*)d_in[1];
    const int*   ei12  = (const int*)d_in[2];
    const int*   ei21  = (const int*)d_in[3];
    const int*   pidx  = (const int*)d_in[4];
    const float* Win1  = (const float*)d_in[5];
    const float* bin1  = (const float*)d_in[6];
    const float* Win2  = (const float*)d_in[7];
    const float* bin2  = (const float*)d_in[8];
    const float* Wk    = (const float*)d_in[9];
    const float* bk    = (const float*)d_in[10];
    const float* Wq    = (const float*)d_in[11];
    const float* bq    = (const float*)d_in[12];
    const float* Wv    = (const float*)d_in[13];
    const float* bv    = (const float*)d_in[14];
    const float* Wa    = (const float*)d_in[15];
    const float* ba    = (const float*)d_in[16];
    const float* skip  = (const float*)d_in[17];
    const float* arel  = (const float*)d_in[18];
    const float* mrel  = (const float*)d_in[19];
    const float* prior = (const float*)d_in[20];
    float* out = (float*)d_out;

    const int E = in_sizes[2] / 2;
    const int P = in_sizes[4] / 2;

    float *h1, *h2, *agg1, *agg2, *Em, *Ed, *Wcat, *bcat;
    __half *qkv1, *qkv2;
    int *rp12, *rp21, *src12, *src21;
    cudaGetSymbolAddress((void**)&h1,   g_h1);
    cudaGetSymbolAddress((void**)&h2,   g_h2);
    cudaGetSymbolAddress((void**)&qkv1, g_qkv1);
    cudaGetSymbolAddress((void**)&qkv2, g_qkv2);
    cudaGetSymbolAddress((void**)&agg1, g_agg1);
    cudaGetSymbolAddress((void**)&agg2, g_agg2);
    cudaGetSymbolAddress((void**)&Em,   g_Em);
    cudaGetSymbolAddress((void**)&Ed,   g_Ed);
    cudaGetSymbolAddress((void**)&Wcat, g_Wcat);
    cudaGetSymbolAddress((void**)&bcat, g_bcat);
    cudaGetSymbolAddress((void**)&rp12, g_rp12);
    cudaGetSymbolAddress((void**)&rp21, g_rp21);
    cudaGetSymbolAddress((void**)&src12, g_src12);
    cudaGetSymbolAddress((void**)&src21, g_src21);

    const int WW = CHID * CHID;

    prep_cat<<<32 + (CN1 + 255) / 256, 256>>>(Wq, bq, Wk, bk, Wv, bv, arel, mrel);
    csr_hist<<<(E + 255) / 256, 256>>>(ei12, ei21, E);
    {
        int shbytes = (CN1 + 1024) * sizeof(int);
        csr_scan<<<2, 1024, shbytes>>>(CN1);
    }
    csr_scatter<<<(E + 255) / 256, 256>>>(ei12, ei21, E);

    {
        GJob j0 = { x1, CF_IN, Win1, CHID, bin1, h1, CHID, nullptr, 0, CN1, CF_IN, nullptr, 0, nullptr };
        GJob j1 = { x2, CF_IN, Win2, CHID, bin2, h2, CHID, nullptr, 0, CN2, CF_IN, nullptr, 0, nullptr };
        gemm_tc<<<dim3((CN1 + 127) / 128, 1, 2), 256>>>(j0, j1, 1);
    }

    for (int l = 0; l < CNL; l++) {
        const float* A1 = (l == 0) ? h1 : Em;
        const float* A2 = (l == 0) ? h2 : Ed;
        int lda = (l == 0) ? CHID : CNL * CHID;
        int c0 = l * 2 + 0, c1 = l * 2 + 1;

        {
            GJob j0 = { A1, lda, Wcat + (size_t)c0 * CHID * QKVW, QKVW, bcat + c0 * QKVW,
                        nullptr, 0, qkv1, QKVW, CN1, CHID, nullptr, 0, nullptr };
            GJob j1 = { A2, lda, Wcat + (size_t)c1 * CHID * QKVW, QKVW, bcat + c1 * QKVW,
                        nullptr, 0, qkv2, QKVW, CN2, CHID, nullptr, 0, nullptr };
            gemm_tc<<<dim3((CN1 + 127) / 128, 3, 2), 256>>>(j0, j1, 3);
        }

        {
            AJob a = { rp12, src12, qkv2, qkv1, prior + c0 * CNH, agg2, CN2 };
            AJob b = { rp21, src21, qkv1, qkv2, prior + c1 * CNH, agg1, CN1 };
            int warps = CN1 + CN2;
            attend_csr<<<(warps * 32 + 127) / 128, 128>>>(a, b);
        }

        {
            const float* hold1 = (l == 0) ? h1 : Em;
            const float* hold2 = (l == 0) ? h2 : Ed;
            int ldh = (l == 0) ? CHID : CNL * CHID;
            GJob j0 = { agg1, CHID, Wa + (size_t)c0 * WW, CHID, ba + c0 * CHID,
                        Em + l * CHID, CNL * CHID, nullptr, 0, CN1, CHID, hold1, ldh, skip + c0 };
            GJob j1 = { agg2, CHID, Wa + (size_t)c1 * WW, CHID, ba + c1 * CHID,
                        Ed + l * CHID, CNL * CHID, nullptr, 0, CN2, CHID, hold2, ldh, skip + c1 };
            gemm_tc<<<dim3((CN1 + 127) / 128, 1, 2), 256>>>(j0, j1, 2);
        }
    }

    pred_kernel<<<(P * 32 + 255) / 256, 256>>>(pidx, P, out);
}

// round 16
// speedup vs baseline: 1.2683x; 1.0037x over previous
#include <cuda_runtime.h>
#include <cuda_fp16.h>
#include <math.h>

#define CN1 10000
#define CN2 10000
#define CF_IN 256
#define CHID 128
#define CNH 8
#define CDH 16
#define CNL 2
#define QKVW 384
#define EMAX 480000

// ---------------- scratch (static device globals) ----------------
__device__ float  g_h1[CN1 * CHID];
__device__ float  g_h2[CN2 * CHID];
__device__ __half g_qkv1[CN1 * QKVW];
__device__ __half g_qkv2[CN2 * QKVW];
__device__ float  g_agg1[CN1 * CHID], g_agg2[CN2 * CHID];
__device__ float  g_Em[CN1 * CHID * CNL], g_Ed[CN2 * CHID * CNL];
__device__ float  g_Wcat[CNL * 2 * CHID * QKVW];
__device__ float  g_bcat[CNL * 2 * QKVW];
// CSR scratch
__device__ int g_cnt12[CN2], g_cnt21[CN1];
__device__ int g_rp12[CN2 + 1], g_rp21[CN1 + 1];
__device__ int g_pos12[EMAX], g_pos21[EMAX];
__device__ int g_src12[EMAX], g_src21[EMAX];

// ---------------- helpers ----------------
__device__ __forceinline__ float gelu_f(float x) {
    float x3 = x * x * x;
    return 0.5f * x * (1.0f + tanhf(0.7978845608028654f * (x + 0.044715f * x3)));
}

__device__ __forceinline__ unsigned f2tf(float x) {
    unsigned r;
    asm("cvt.rna.tf32.f32 %0, %1;" : "=r"(r) : "f"(x));
    return r;
}

// ---------------- build packed weights: 32 parallel blocks ----------------
__global__ void prep_cat(const float* __restrict__ Wq, const float* __restrict__ bq,
                         const float* __restrict__ Wk, const float* __restrict__ bk,
                         const float* __restrict__ Wv, const float* __restrict__ bv,
                         const float* __restrict__ arel, const float* __restrict__ mrel) {
    int combo = blockIdx.x >> 3;
    int part  = blockIdx.x & 7;
    const int WW = CHID * CHID;
    const int CHUNK = CHID * QKVW / 8;   // 6144
    float* Wcat = g_Wcat + (size_t)combo * CHID * QKVW;
    float* bcat = g_bcat + combo * QKVW;
    int tid = threadIdx.x;
    for (int i = part * CHUNK + tid; i < (part + 1) * CHUNK; i += blockDim.x) {
        int c = i / QKVW, col = i % QKVW;
        float val;
        if (col < 128) {
            val = Wq[(size_t)combo * WW + c * CHID + col];
        } else if (col < 256) {
            int cc = col - 128, h = cc >> 4, e = cc & 15;
            const float* rel = arel + (size_t)combo * CNH * CDH * CDH + h * CDH * CDH;
            float acc = 0.f;
#pragma unroll
            for (int d = 0; d < CDH; d++)
                acc += Wk[(size_t)combo * WW + c * CHID + h * CDH + d] * rel[d * CDH + e];
            val = acc;
        } else {
            int cc = col - 256, h = cc >> 4, e = cc & 15;
            const float* rel = mrel + (size_t)combo * CNH * CDH * CDH + h * CDH * CDH;
            float acc = 0.f;
#pragma unroll
            for (int d = 0; d < CDH; d++)
                acc += Wv[(size_t)combo * WW + c * CHID + h * CDH + d] * rel[d * CDH + e];
            val = acc;
        }
        Wcat[i] = val;
    }
    if (part == 0 && tid < QKVW) {
        int col = tid;
        float val;
        if (col < 128) {
            val = bq[combo * CHID + col];
        } else if (col < 256) {
            int cc = col - 128, h = cc >> 4, e = cc & 15;
            const float* rel = arel + (size_t)combo * CNH * CDH * CDH + h * CDH * CDH;
            float acc = 0.f;
#pragma unroll
            for (int d = 0; d < CDH; d++) acc += bk[combo * CHID + h * CDH + d] * rel[d * CDH + e];
            val = acc;
        } else {
            int cc = col - 256, h = cc >> 4, e = cc & 15;
            const float* rel = mrel + (size_t)combo * CNH * CDH * CDH + h * CDH * CDH;
            float acc = 0.f;
#pragma unroll
            for (int d = 0; d < CDH; d++) acc += bv[combo * CHID + h * CDH + d] * rel[d * CDH + e];
            val = acc;
        }
        bcat[col] = val;
    }
}

// ---------------- CSR build (runs on side stream) ----------------
__global__ void csr_zero() {
    int i = blockIdx.x * blockDim.x + threadIdx.x;
    if (i < CN2) g_cnt12[i] = 0;
    if (i < CN1) g_cnt21[i] = 0;
}

__global__ void csr_hist(const int* __restrict__ ei12, const int* __restrict__ ei21, int E) {
    int i = blockIdx.x * blockDim.x + threadIdx.x;
    if (i < E) {
        g_pos12[i] = atomicAdd(&g_cnt12[ei12[E + i]], 1);
        g_pos21[i] = atomicAdd(&g_cnt21[ei21[E + i]], 1);
    }
}

__global__ void __launch_bounds__(1024) csr_scan(int n) {
    int dir = blockIdx.x;
    const int* cnt = dir ? g_cnt21 : g_cnt12;
    int* rp  = dir ? g_rp21 : g_rp12;
    extern __shared__ int sh[];
    int* vals = sh;
    int* sums = sh + n;
    int t = threadIdx.x;
    for (int i = t; i < n; i += 1024) vals[i] = cnt[i];
    __syncthreads();
    int chunk = (n + 1023) / 1024;
    int s0 = t * chunk;
    int local = 0;
    for (int i = 0; i < chunk; i++) if (s0 + i < n) local += vals[s0 + i];
    sums[t] = local;
    __syncthreads();
    for (int off = 1; off < 1024; off <<= 1) {
        int v = (t >= off) ? sums[t - off] : 0;
        __syncthreads();
        sums[t] += v;
        __syncthreads();
    }
    int run = (t == 0) ? 0 : sums[t - 1];
    int total = sums[1023];
    __syncthreads();
    for (int i = 0; i < chunk; i++) if (s0 + i < n) {
        int c = vals[s0 + i];
        vals[s0 + i] = run;
        run += c;
    }
    __syncthreads();
    for (int i = t; i < n; i += 1024) rp[i] = vals[i];
    if (t == 0) rp[n] = total;
}

__global__ void csr_scatter(const int* __restrict__ ei12, const int* __restrict__ ei21, int E) {
    int i = blockIdx.x * blockDim.x + threadIdx.x;
    if (i < E) {
        int d1 = ei12[E + i];
        int d2 = ei21[E + i];
        g_src12[g_rp12[d1] + g_pos12[i]] = ei12[i];
        g_src21[g_rp21[d2] + g_pos21[i]] = ei21[i];
    }
}

// ---------------- TF32 tensor-core GEMM: two jobs per launch (blockIdx.z) ----------------
struct GJob {
    const float* A; int lda;
    const float* B; int ldb;
    const float* bias;
    float* Cf; int ldcf;
    __half* Ch; int ldch;
    int M, K;
    const float* hold; int ldh;
    const float* skipp;
};

__global__ void __launch_bounds__(256)
gemm_tc(GJob j0, GJob j1, int mode) {
    GJob jb = blockIdx.z ? j1 : j0;
    __shared__ unsigned As[128][36];
    __shared__ unsigned Bs[32][136];

    int tid  = threadIdx.x;
    int warp = tid >> 5;
    int lane = tid & 31;
    int g = lane >> 2;
    int c = lane & 3;
    int warp_m = warp >> 2;
    int warp_n = warp & 3;
    int m0 = blockIdx.x * 128;
    int n0 = blockIdx.y * 128;

    float acc[4][4][4];
#pragma unroll
    for (int mi = 0; mi < 4; mi++)
#pragma unroll
        for (int ni = 0; ni < 4; ni++)
#pragma unroll
            for (int r = 0; r < 4; r++) acc[mi][ni][r] = 0.f;

    for (int k0 = 0; k0 < jb.K; k0 += 32) {
#pragma unroll
        for (int i = 0; i < 4; i++) {
            int lin = tid + i * 256;
            int row = lin >> 3;
            int kc4 = (lin & 7) << 2;
            float4 v = make_float4(0.f, 0.f, 0.f, 0.f);
            int m = m0 + row;
            if (m < jb.M) {
                v = *(const float4*)(jb.A + (size_t)m * jb.lda + k0 + kc4);
                if (mode == 2) {
                    v.x = gelu_f(v.x); v.y = gelu_f(v.y);
                    v.z = gelu_f(v.z); v.w = gelu_f(v.w);
                }
            }
            uint4 t;
            t.x = f2tf(v.x); t.y = f2tf(v.y); t.z = f2tf(v.z); t.w = f2tf(v.w);
            *(uint4*)&As[row][kc4] = t;
        }
#pragma unroll
        for (int i = 0; i < 4; i++) {
            int lin = tid + i * 256;
            int kr  = lin >> 5;
            int nc4 = (lin & 31) << 2;
            float4 v = *(const float4*)(jb.B + (size_t)(k0 + kr) * jb.ldb + n0 + nc4);
            uint4 t;
            t.x = f2tf(v.x); t.y = f2tf(v.y); t.z = f2tf(v.z); t.w = f2tf(v.w);
            *(uint4*)&Bs[kr][nc4] = t;
        }
        __syncthreads();

#pragma unroll
        for (int ks = 0; ks < 4; ks++) {
            int kk = ks * 8;
            unsigned a[4][4];
#pragma unroll
            for (int mi = 0; mi < 4; mi++) {
                int r0 = warp_m * 64 + mi * 16 + g;
                a[mi][0] = As[r0][kk + c];
                a[mi][1] = As[r0 + 8][kk + c];
                a[mi][2] = As[r0][kk + c + 4];
                a[mi][3] = As[r0 + 8][kk + c + 4];
            }
            unsigned b[4][2];
#pragma unroll
            for (int ni = 0; ni < 4; ni++) {
                int nn = warp_n * 32 + ni * 8 + g;
                b[ni][0] = Bs[kk + c][nn];
                b[ni][1] = Bs[kk + c + 4][nn];
            }
#pragma unroll
            for (int mi = 0; mi < 4; mi++)
#pragma unroll
                for (int ni = 0; ni < 4; ni++) {
                    asm volatile(
                        "mma.sync.aligned.m16n8k8.row.col.f32.tf32.tf32.f32 "
                        "{%0,%1,%2,%3}, {%4,%5,%6,%7}, {%8,%9}, {%0,%1,%2,%3};\n"
                        : "+f"(acc[mi][ni][0]), "+f"(acc[mi][ni][1]),
                          "+f"(acc[mi][ni][2]), "+f"(acc[mi][ni][3])
                        : "r"(a[mi][0]), "r"(a[mi][1]), "r"(a[mi][2]), "r"(a[mi][3]),
                          "r"(b[ni][0]), "r"(b[ni][1]));
                }
        }
        __syncthreads();
    }

    float sg = 1.f, sg1 = 0.f;
    if (mode == 2) {
        sg = 1.0f / (1.0f + __expf(-*jb.skipp));
        sg1 = 1.0f - sg;
    }

#pragma unroll
    for (int mi = 0; mi < 4; mi++) {
#pragma unroll
        for (int half = 0; half < 2; half++) {
            int r = m0 + warp_m * 64 + mi * 16 + g + half * 8;
            if (r >= jb.M) continue;
#pragma unroll
            for (int ni = 0; ni < 4; ni++) {
                int n = n0 + warp_n * 32 + ni * 8 + 2 * c;
                float x0 = acc[mi][ni][half * 2 + 0] + jb.bias[n + 0];
                float x1 = acc[mi][ni][half * 2 + 1] + jb.bias[n + 1];
                if (mode == 1) {
                    x0 = fmaxf(x0, 0.f); x1 = fmaxf(x1, 0.f);
                    *(float2*)(jb.Cf + (size_t)r * jb.ldcf + n) = make_float2(x0, x1);
                } else if (mode == 2) {
                    const float* hp = jb.hold + (size_t)r * jb.ldh + n;
                    *(float2*)(jb.Cf + (size_t)r * jb.ldcf + n) =
                        make_float2(sg * x0 + sg1 * hp[0], sg * x1 + sg1 * hp[1]);
                } else {
                    __half2 p = __floats2half2_rn(x0, x1);
                    *(__half2*)(jb.Ch + (size_t)r * jb.ldch + n) = p;
                }
            }
        }
    }
}

// ---------------- CSR attention: warp = 1 dst, two 16-lane teams, lean pair loop ----------------
struct AJob {
    const int* rp; const int* col;
    const __half* qkv_dst; const __half* qkv_src;
    const float* prior;
    float* agg;
    int n;
};

__device__ __forceinline__ void team_edge(uint4 kw, uint4 vw, bool valid,
                                          const __half2* qh, float scale,
                                          float* acc, float& ssum) {
    const __half2* kh = (const __half2*)&kw;
    __half2 p = __hmul2(qh[0], kh[0]);
    p = __hfma2(qh[1], kh[1], p);
    p = __hfma2(qh[2], kh[2], p);
    p = __hfma2(qh[3], kh[3], p);
    float2 df = __half22float2(p);
    float d = df.x + df.y;
    d += __shfl_xor_sync(0xffffffffu, d, 1);
    float e = valid ? __expf(d * scale) : 0.f;
    ssum += e;
    const __half2* vh = (const __half2*)&vw;
#pragma unroll
    for (int i = 0; i < 4; i++) {
        float2 vf = __half22float2(vh[i]);
        acc[2 * i]     += e * vf.x;
        acc[2 * i + 1] += e * vf.y;
    }
}

__global__ void __launch_bounds__(128, 8)
attend_csr(AJob a, AJob b) {
    int gw = (blockIdx.x * blockDim.x + threadIdx.x) >> 5;
    int lane = threadIdx.x & 31;
    int tlane = lane & 15;
    int team  = lane >> 4;
    int total = a.n + b.n;
    if (gw >= total) return;
    AJob jb = (gw < a.n) ? a : b;
    int dst = (gw < a.n) ? gw : gw - a.n;

    int start = __ldg(jb.rp + dst);
    int end   = __ldg(jb.rp + dst + 1);

    uint4 qw = __ldg((const uint4*)(jb.qkv_dst + (size_t)dst * QKVW) + tlane);
    __half2 qh[4];
    qh[0] = *(__half2*)&qw.x; qh[1] = *(__half2*)&qw.y;
    qh[2] = *(__half2*)&qw.z; qh[3] = *(__half2*)&qw.w;
    int h = tlane >> 1;
    float scale = __ldg(jb.prior + h) * 0.25f;

    const uint4* srcb = (const uint4*)jb.qkv_src;   // 48 uint4 per row

    float acc[8];
#pragma unroll
    for (int i = 0; i < 8; i++) acc[i] = 0.f;
    float ssum = 0.f;

    for (int base = start; base < end; base += 32) {
        int myc = (base + lane < end) ? __ldg(jb.col + base + lane) : 0;
        int cnt = min(32, end - base);
        int pairs = cnt >> 1;
        // unconditional pair loop: team 0 = even edges, team 1 = odd edges
        for (int it = 0; it < pairs; it++) {
            int s0 = __shfl_sync(0xffffffffu, myc, 2 * it + team);
            const uint4* p0 = srcb + s0 * 48 + 16 + tlane;
            uint4 k0 = __ldg(p0), v0 = __ldg(p0 + 16);
            team_edge(k0, v0, true, qh, scale, acc, ssum);
        }
        if (cnt & 1) {   // single tail edge: team 0 computes, team 1 contributes 0
            int s0 = __shfl_sync(0xffffffffu, myc, cnt - 1);
            const uint4* p0 = srcb + s0 * 48 + 16 + tlane;
            uint4 k0 = __ldg(p0), v0 = __ldg(p0 + 16);
            team_edge(k0, v0, team == 0, qh, scale, acc, ssum);
        }
    }

#pragma unroll
    for (int i = 0; i < 8; i++) acc[i] += __shfl_xor_sync(0xffffffffu, acc[i], 16);
    ssum += __shfl_xor_sync(0xffffffffu, ssum, 16);

    if (team == 0) {
        float inv = 1.0f / (ssum + 1e-16f);
        float* op = jb.agg + (size_t)dst * CHID + tlane * 8;
        *(float4*)(op)     = make_float4(acc[0] * inv, acc[1] * inv, acc[2] * inv, acc[3] * inv);
        *(float4*)(op + 4) = make_float4(acc[4] * inv, acc[5] * inv, acc[6] * inv, acc[7] * inv);
    }
}

// ---------------- final pair scores ----------------
__global__ void __launch_bounds__(256)
pred_kernel(const int* __restrict__ pidx, int P, float* __restrict__ out) {
    int warp = (blockIdx.x * blockDim.x + threadIdx.x) >> 5;
    int lane = threadIdx.x & 31;
    if (warp >= P) return;
    int i = pidx[warp];
    int j = pidx[P + warp];
    const float4* em = (const float4*)(g_Em + (size_t)i * (CHID * CNL));
    const float4* ed = (const float4*)(g_Ed + (size_t)j * (CHID * CNL));
    float4 a0 = em[lane],      b0 = ed[lane];
    float4 a1 = em[32 + lane], b1 = ed[32 + lane];
    float d = a0.x * b0.x + a0.y * b0.y + a0.z * b0.z + a0.w * b0.w
            + a1.x * b1.x + a1.y * b1.y + a1.z * b1.z + a1.w * b1.w;
#pragma unroll
    for (int o = 16; o > 0; o >>= 1) d += __shfl_xor_sync(0xffffffffu, d, o);
    if (lane == 0) out[warp] = d;
}

// ---------------- host driver ----------------
extern "C" void kernel_launch(void* const* d_in, const int* in_sizes, int n_in,
                              void* d_out, int out_size) {
    const float* x1    = (const float*)d_in[0];
    const float* x2    = (const float*)d_in[1];
    const int*   ei12  = (const int*)d_in[2];
    const int*   ei21  = (const int*)d_in[3];
    const int*   pidx  = (const int*)d_in[4];
    const float* Win1  = (const float*)d_in[5];
    const float* bin1  = (const float*)d_in[6];
    const float* Win2  = (const float*)d_in[7];
    const float* bin2  = (const float*)d_in[8];
    const float* Wk    = (const float*)d_in[9];
    const float* bk    = (const float*)d_in[10];
    const float* Wq    = (const float*)d_in[11];
    const float* bq    = (const float*)d_in[12];
    const float* Wv    = (const float*)d_in[13];
    const float* bv    = (const float*)d_in[14];
    const float* Wa    = (const float*)d_in[15];
    const float* ba    = (const float*)d_in[16];
    const float* skip  = (const float*)d_in[17];
    const float* arel  = (const float*)d_in[18];
    const float* mrel  = (const float*)d_in[19];
    const float* prior = (const float*)d_in[20];
    float* out = (float*)d_out;

    const int E = in_sizes[2] / 2;
    const int P = in_sizes[4] / 2;

    float *h1, *h2, *agg1, *agg2, *Em, *Ed, *Wcat, *bcat;
    __half *qkv1, *qkv2;
    int *rp12, *rp21, *src12, *src21;
    cudaGetSymbolAddress((void**)&h1,   g_h1);
    cudaGetSymbolAddress((void**)&h2,   g_h2);
    cudaGetSymbolAddress((void**)&qkv1, g_qkv1);
    cudaGetSymbolAddress((void**)&qkv2, g_qkv2);
    cudaGetSymbolAddress((void**)&agg1, g_agg1);
    cudaGetSymbolAddress((void**)&agg2, g_agg2);
    cudaGetSymbolAddress((void**)&Em,   g_Em);
    cudaGetSymbolAddress((void**)&Ed,   g_Ed);
    cudaGetSymbolAddress((void**)&Wcat, g_Wcat);
    cudaGetSymbolAddress((void**)&bcat, g_bcat);
    cudaGetSymbolAddress((void**)&rp12, g_rp12);
    cudaGetSymbolAddress((void**)&rp21, g_rp21);
    cudaGetSymbolAddress((void**)&src12, g_src12);
    cudaGetSymbolAddress((void**)&src21, g_src21);

    const int WW = CHID * CHID;

    // Fork the CSR build onto a side stream so it overlaps prep_cat + input/qkv GEMMs.
    // (stream/event host objects; kernel_launch only runs twice, replays use the graph)
    cudaStream_t s2;
    cudaStreamCreate(&s2);
    cudaEvent_t evFork, evJoin;
    cudaEventCreateWithFlags(&evFork, cudaEventDisableTiming);
    cudaEventCreateWithFlags(&evJoin, cudaEventDisableTiming);

    cudaEventRecord(evFork, 0);
    cudaStreamWaitEvent(s2, evFork, 0);
    csr_zero<<<(CN1 + 255) / 256, 256, 0, s2>>>();
    csr_hist<<<(E + 255) / 256, 256, 0, s2>>>(ei12, ei21, E);
    {
        int shbytes = (CN1 + 1024) * sizeof(int);
        csr_scan<<<2, 1024, shbytes, s2>>>(CN1);
    }
    csr_scatter<<<(E + 255) / 256, 256, 0, s2>>>(ei12, ei21, E);
    cudaEventRecord(evJoin, s2);

    // main stream: weights + dense phase
    prep_cat<<<32, 256>>>(Wq, bq, Wk, bk, Wv, bv, arel, mrel);
    {
        GJob j0 = { x1, CF_IN, Win1, CHID, bin1, h1, CHID, nullptr, 0, CN1, CF_IN, nullptr, 0, nullptr };
        GJob j1 = { x2, CF_IN, Win2, CHID, bin2, h2, CHID, nullptr, 0, CN2, CF_IN, nullptr, 0, nullptr };
        gemm_tc<<<dim3((CN1 + 127) / 128, 1, 2), 256>>>(j0, j1, 1);
    }

    bool joined = false;
    for (int l = 0; l < CNL; l++) {
        const float* A1 = (l == 0) ? h1 : Em;
        const float* A2 = (l == 0) ? h2 : Ed;
        int lda = (l == 0) ? CHID : CNL * CHID;
        int c0 = l * 2 + 0, c1 = l * 2 + 1;

        {
            GJob j0 = { A1, lda, Wcat + (size_t)c0 * CHID * QKVW, QKVW, bcat + c0 * QKVW,
                        nullptr, 0, qkv1, QKVW, CN1, CHID, nullptr, 0, nullptr };
            GJob j1 = { A2, lda, Wcat + (size_t)c1 * CHID * QKVW, QKVW, bcat + c1 * QKVW,
                        nullptr, 0, qkv2, QKVW, CN2, CHID, nullptr, 0, nullptr };
            gemm_tc<<<dim3((CN1 + 127) / 128, 3, 2), 256>>>(j0, j1, 3);
        }

        if (!joined) {              // CSR must be ready before first attend
            cudaStreamWaitEvent(0, evJoin, 0);
            joined = true;
        }

        {
            AJob a = { rp12, src12, qkv2, qkv1, prior + c0 * CNH, agg2, CN2 };
            AJob b = { rp21, src21, qkv1, qkv2, prior + c1 * CNH, agg1, CN1 };
            int warps = CN1 + CN2;
            attend_csr<<<(warps * 32 + 127) / 128, 128>>>(a, b);
        }

        {
            const float* hold1 = (l == 0) ? h1 : Em;
            const float* hold2 = (l == 0) ? h2 : Ed;
            int ldh = (l == 0) ? CHID : CNL * CHID;
            GJob j0 = { agg1, CHID, Wa + (size_t)c0 * WW, CHID, ba + c0 * CHID,
                        Em + l * CHID, CNL * CHID, nullptr, 0, CN1, CHID, hold1, ldh, skip + c0 };
            GJob j1 = { agg2, CHID, Wa + (size_t)c1 * WW, CHID, ba + c1 * CHID,
                        Ed + l * CHID, CNL * CHID, nullptr, 0, CN2, CHID, hold2, ldh, skip + c1 };
            gemm_tc<<<dim3((CN1 + 127) / 128, 1, 2), 256>>>(j0, j1, 2);
        }
    }

    pred_kernel<<<(P * 32 + 255) / 256, 256>>>(pidx, P, out);
}